// round 1
// baseline (speedup 1.0000x reference)
#include <cuda_runtime.h>
#include <math.h>

#define B_  2
#define T_  4096
#define C_  1024
#define H_  16
#define HD_ 64
#define W_  256
#define NW_ (T_/W_)
#define M_  (B_*T_)

// Scratch (no cudaMalloc allowed)
__device__ float g_q[(size_t)M_*C_];
__device__ float g_k[(size_t)M_*C_];
__device__ float g_v[(size_t)M_*C_];
__device__ float g_y[(size_t)M_*C_];

// ---------------------------------------------------------------------------
// SGEMM (NT): C[m][n] = sum_k A[m][k] * Wt[n][k]
// A: [M,K] row-major, Wt: [N,K] row-major (both K-contiguous -> coalesced).
// Tile 128x128x32, 256 threads, 8x8 register blocking (4+4 split rows/cols).
// ROPE=1: apply rotary embedding in the epilogue (pairs along n, t = m % T_).
// ---------------------------------------------------------------------------
template<int ROPE>
__global__ __launch_bounds__(256, 2)
void gemm_nt(const float* __restrict__ A, const float* __restrict__ Wt,
             float* __restrict__ Cout, int M, int N, int K)
{
    const int BM = 128, BN = 128, BK = 32;
    __shared__ float As[BK][BM];
    __shared__ float Bs[BK][BN];

    const int tid = threadIdx.x;
    const int m0 = blockIdx.y * BM;
    const int n0 = blockIdx.x * BN;

    // global-load mapping: 32 rows per pass, 8 float4 per row (128B contiguous/row)
    const int lr = tid >> 3;          // row 0..31 within pass
    const int lc = (tid & 7) * 4;     // k offset 0..28

    // compute mapping
    const int tx = tid & 15;          // 16 col-threads
    const int ty = tid >> 4;          // 16 row-threads

    float acc[8][8];
#pragma unroll
    for (int i = 0; i < 8; i++)
#pragma unroll
        for (int j = 0; j < 8; j++) acc[i][j] = 0.f;

    for (int k0 = 0; k0 < K; k0 += BK) {
#pragma unroll
        for (int p = 0; p < 4; p++) {
            int r = lr + p * 32;
            float4 va = *(const float4*)(A + (size_t)(m0 + r) * K + k0 + lc);
            As[lc + 0][r] = va.x; As[lc + 1][r] = va.y;
            As[lc + 2][r] = va.z; As[lc + 3][r] = va.w;
            float4 vb = *(const float4*)(Wt + (size_t)(n0 + r) * K + k0 + lc);
            Bs[lc + 0][r] = vb.x; Bs[lc + 1][r] = vb.y;
            Bs[lc + 2][r] = vb.z; Bs[lc + 3][r] = vb.w;
        }
        __syncthreads();

#pragma unroll
        for (int kk = 0; kk < BK; kk++) {
            float a[8], b[8];
            *(float4*)&a[0] = *(const float4*)&As[kk][ty * 4];
            *(float4*)&a[4] = *(const float4*)&As[kk][ty * 4 + 64];
            *(float4*)&b[0] = *(const float4*)&Bs[kk][tx * 4];
            *(float4*)&b[4] = *(const float4*)&Bs[kk][tx * 4 + 64];
#pragma unroll
            for (int i = 0; i < 8; i++)
#pragma unroll
                for (int j = 0; j < 8; j++)
                    acc[i][j] += a[i] * b[j];
        }
        __syncthreads();
    }

    if (ROPE) {
        // inv_freq per column-pair (4 pairs per thread along n), hoisted, double-exact
        float invf[4];
#pragma unroll
        for (int jp = 0; jp < 4; jp++) {
            int j = jp * 2;
            int nn = n0 + (tx << 2) + (j & 3) + ((j & 4) << 4);
            int ip = (nn & (HD_ - 1)) >> 1;   // 0..31
            invf[jp] = (float)exp(-0.28782313662425572 * (double)ip); // ln(1e4)/32
        }
#pragma unroll
        for (int i = 0; i < 8; i++) {
            int mm = m0 + (ty << 2) + (i & 3) + ((i & 4) << 4);
            float tpos = (float)(mm & (T_ - 1));
#pragma unroll
            for (int jp = 0; jp < 4; jp++) {
                int j = jp * 2;
                int nn = n0 + (tx << 2) + (j & 3) + ((j & 4) << 4);
                float sv, cv;
                sincosf(tpos * invf[jp], &sv, &cv);
                float x1 = acc[i][j], x2 = acc[i][j + 1];
                Cout[(size_t)mm * N + nn]     = x1 * cv - x2 * sv;
                Cout[(size_t)mm * N + nn + 1] = x1 * sv + x2 * cv;
            }
        }
    } else {
#pragma unroll
        for (int i = 0; i < 8; i++) {
            int mm = m0 + (ty << 2) + (i & 3) + ((i & 4) << 4);
#pragma unroll
            for (int j = 0; j < 8; j++) {
                int nn = n0 + (tx << 2) + (j & 3) + ((j & 4) << 4);
                Cout[(size_t)mm * N + nn] = acc[i][j];
            }
        }
    }
}

// ---------------------------------------------------------------------------
// Windowed attention. Grid (nW, H, B). 512 threads: 2 threads / query row,
// each covers 32 of the 64 head dims. K,V staged in 131KB dynamic smem.
// Online (streaming) softmax, output normalized and written to [B,T,C].
// ---------------------------------------------------------------------------
__global__ __launch_bounds__(512, 1)
void attn_win(const float* __restrict__ Q, const float* __restrict__ Kg,
              const float* __restrict__ Vg, float* __restrict__ Y)
{
    extern __shared__ float sm[];
    float* Ks = sm;                 // [256][64]
    float* Vs = sm + W_ * HD_;      // [256][64]

    const int w = blockIdx.x, h = blockIdx.y, b = blockIdx.z;
    const int tid = threadIdx.x;
    const size_t base = ((size_t)(b * T_ + w * W_)) * C_ + h * HD_;

    // cooperative coalesced load of K,V tiles (float4, contiguous per row)
    const int nf4 = W_ * HD_ / 4;   // 4096 float4
    for (int idx = tid; idx < nf4; idx += 512) {
        int row = idx >> 4;         // HD_/4 = 16 float4 per row
        int d4  = idx & 15;
        ((float4*)Ks)[idx] = *((const float4*)(Kg + base + (size_t)row * C_) + d4);
        ((float4*)Vs)[idx] = *((const float4*)(Vg + base + (size_t)row * C_) + d4);
    }

    const int qi = tid >> 1;        // query row 0..255
    const int hf = tid & 1;         // which 32-dim half

    float q[32];
    {
        const float4* qp = (const float4*)(Q + base + (size_t)qi * C_ + hf * 32);
#pragma unroll
        for (int j = 0; j < 8; j++) *(float4*)&q[j * 4] = qp[j];
    }
    __syncthreads();

    float m = -1e30f, l = 0.f;
    float o[32];
#pragma unroll
    for (int d = 0; d < 32; d++) o[d] = 0.f;
    const float scale = 0.125f;     // 1/sqrt(64)

    for (int kj = 0; kj < W_; kj++) {
        const float* kr = Ks + kj * HD_ + hf * 32;
        float p = 0.f;
#pragma unroll
        for (int j = 0; j < 8; j++) {
            float4 kv = *(const float4*)(kr + j * 4);
            p += q[j*4+0] * kv.x + q[j*4+1] * kv.y + q[j*4+2] * kv.z + q[j*4+3] * kv.w;
        }
        float s = (p + __shfl_xor_sync(0xffffffffu, p, 1)) * scale;

        float mn   = fmaxf(m, s);
        float corr = __expf(m - mn);
        float pe   = __expf(s - mn);
        l = l * corr + pe;

        const float* vr = Vs + kj * HD_ + hf * 32;
#pragma unroll
        for (int j = 0; j < 8; j++) {
            float4 vv = *(const float4*)(vr + j * 4);
            o[j*4+0] = o[j*4+0] * corr + pe * vv.x;
            o[j*4+1] = o[j*4+1] * corr + pe * vv.y;
            o[j*4+2] = o[j*4+2] * corr + pe * vv.z;
            o[j*4+3] = o[j*4+3] * corr + pe * vv.w;
        }
        m = mn;
    }

    float inv = 1.f / l;
    float* dst = Y + base + (size_t)qi * C_ + hf * 32;
#pragma unroll
    for (int j = 0; j < 8; j++) {
        float4 v = make_float4(o[j*4+0]*inv, o[j*4+1]*inv, o[j*4+2]*inv, o[j*4+3]*inv);
        *(float4*)(dst + j * 4) = v;
    }
}

// ---------------------------------------------------------------------------
extern "C" void kernel_launch(void* const* d_in, const int* in_sizes, int n_in,
                              void* d_out, int out_size)
{
    const float* x  = (const float*)d_in[0];
    const float* wq = (const float*)d_in[1];
    const float* wk = (const float*)d_in[2];
    const float* wv = (const float*)d_in[3];
    const float* wo = (const float*)d_in[4];
    float* out = (float*)d_out;

    float *q, *k, *v, *y;
    cudaGetSymbolAddress((void**)&q, g_q);
    cudaGetSymbolAddress((void**)&k, g_k);
    cudaGetSymbolAddress((void**)&v, g_v);
    cudaGetSymbolAddress((void**)&y, g_y);

    dim3 gg(C_ / 128, M_ / 128);
    gemm_nt<1><<<gg, 256>>>(x, wq, q, M_, C_, C_);
    gemm_nt<1><<<gg, 256>>>(x, wk, k, M_, C_, C_);
    gemm_nt<0><<<gg, 256>>>(x, wv, v, M_, C_, C_);

    const int smemBytes = 2 * W_ * HD_ * (int)sizeof(float); // 131072
    cudaFuncSetAttribute(attn_win, cudaFuncAttributeMaxDynamicSharedMemorySize, smemBytes);
    dim3 ga(NW_, H_, B_);
    attn_win<<<ga, 512, smemBytes>>>(q, k, v, y);

    gemm_nt<0><<<gg, 256>>>(y, wo, out, M_, C_, C_);
}

// round 2
// speedup vs baseline: 1.0014x; 1.0014x over previous
#include <cuda_runtime.h>
#include <math.h>

#define B_  2
#define T_  4096
#define C_  1024
#define H_  16
#define HD_ 64
#define W_  256
#define NW_ (T_/W_)
#define M_  (B_*T_)

// Scratch (no cudaMalloc allowed)
__device__ float g_q[(size_t)M_*C_];
__device__ float g_k[(size_t)M_*C_];
__device__ float g_v[(size_t)M_*C_];
__device__ float g_y[(size_t)M_*C_];

// ---------------------------------------------------------------------------
// SGEMM (NT): C[m][n] = sum_k A[m][k] * Wt[n][k]
// A: [M,K] row-major, Wt: [N,K] row-major (both K-contiguous -> coalesced).
// Tile 128x128x32, 256 threads, 8x8 register blocking (4+4 split rows/cols).
// ROPE=1: apply rotary embedding in the epilogue (pairs along n, t = m % T_).
// ---------------------------------------------------------------------------
template<int ROPE>
__global__ __launch_bounds__(256, 2)
void gemm_nt(const float* __restrict__ A, const float* __restrict__ Wt,
             float* __restrict__ Cout, int M, int N, int K)
{
    const int BM = 128, BN = 128, BK = 32;
    __shared__ float As[BK][BM];
    __shared__ float Bs[BK][BN];

    const int tid = threadIdx.x;
    const int m0 = blockIdx.y * BM;
    const int n0 = blockIdx.x * BN;

    // global-load mapping: 32 rows per pass, 8 float4 per row (128B contiguous/row)
    const int lr = tid >> 3;          // row 0..31 within pass
    const int lc = (tid & 7) * 4;     // k offset 0..28

    // compute mapping
    const int tx = tid & 15;          // 16 col-threads
    const int ty = tid >> 4;          // 16 row-threads

    float acc[8][8];
#pragma unroll
    for (int i = 0; i < 8; i++)
#pragma unroll
        for (int j = 0; j < 8; j++) acc[i][j] = 0.f;

    for (int k0 = 0; k0 < K; k0 += BK) {
#pragma unroll
        for (int p = 0; p < 4; p++) {
            int r = lr + p * 32;
            float4 va = *(const float4*)(A + (size_t)(m0 + r) * K + k0 + lc);
            As[lc + 0][r] = va.x; As[lc + 1][r] = va.y;
            As[lc + 2][r] = va.z; As[lc + 3][r] = va.w;
            float4 vb = *(const float4*)(Wt + (size_t)(n0 + r) * K + k0 + lc);
            Bs[lc + 0][r] = vb.x; Bs[lc + 1][r] = vb.y;
            Bs[lc + 2][r] = vb.z; Bs[lc + 3][r] = vb.w;
        }
        __syncthreads();

#pragma unroll
        for (int kk = 0; kk < BK; kk++) {
            float a[8], b[8];
            *(float4*)&a[0] = *(const float4*)&As[kk][ty * 4];
            *(float4*)&a[4] = *(const float4*)&As[kk][ty * 4 + 64];
            *(float4*)&b[0] = *(const float4*)&Bs[kk][tx * 4];
            *(float4*)&b[4] = *(const float4*)&Bs[kk][tx * 4 + 64];
#pragma unroll
            for (int i = 0; i < 8; i++)
#pragma unroll
                for (int j = 0; j < 8; j++)
                    acc[i][j] += a[i] * b[j];
        }
        __syncthreads();
    }

    if (ROPE) {
        // inv_freq per column-pair (4 pairs per thread along n), hoisted, double-exact
        float invf[4];
#pragma unroll
        for (int jp = 0; jp < 4; jp++) {
            int j = jp * 2;
            int nn = n0 + (tx << 2) + (j & 3) + ((j & 4) << 4);
            int ip = (nn & (HD_ - 1)) >> 1;   // 0..31
            invf[jp] = (float)exp(-0.28782313662425572 * (double)ip); // ln(1e4)/32
        }
#pragma unroll
        for (int i = 0; i < 8; i++) {
            int mm = m0 + (ty << 2) + (i & 3) + ((i & 4) << 4);
            float tpos = (float)(mm & (T_ - 1));
#pragma unroll
            for (int jp = 0; jp < 4; jp++) {
                int j = jp * 2;
                int nn = n0 + (tx << 2) + (j & 3) + ((j & 4) << 4);
                float sv, cv;
                sincosf(tpos * invf[jp], &sv, &cv);
                float x1 = acc[i][j], x2 = acc[i][j + 1];
                Cout[(size_t)mm * N + nn]     = x1 * cv - x2 * sv;
                Cout[(size_t)mm * N + nn + 1] = x1 * sv + x2 * cv;
            }
        }
    } else {
#pragma unroll
        for (int i = 0; i < 8; i++) {
            int mm = m0 + (ty << 2) + (i & 3) + ((i & 4) << 4);
#pragma unroll
            for (int j = 0; j < 8; j++) {
                int nn = n0 + (tx << 2) + (j & 3) + ((j & 4) << 4);
                Cout[(size_t)mm * N + nn] = acc[i][j];
            }
        }
    }
}

// ---------------------------------------------------------------------------
// Windowed attention. Grid (nW, H, B). 512 threads: 2 threads / query row,
// each covers 32 of the 64 head dims. K,V staged in 131KB dynamic smem.
// Online (streaming) softmax, output normalized and written to [B,T,C].
// ---------------------------------------------------------------------------
__global__ __launch_bounds__(512, 1)
void attn_win(const float* __restrict__ Q, const float* __restrict__ Kg,
              const float* __restrict__ Vg, float* __restrict__ Y)
{
    extern __shared__ float sm[];
    float* Ks = sm;                 // [256][64]
    float* Vs = sm + W_ * HD_;      // [256][64]

    const int w = blockIdx.x, h = blockIdx.y, b = blockIdx.z;
    const int tid = threadIdx.x;
    const size_t base = ((size_t)(b * T_ + w * W_)) * C_ + h * HD_;

    // cooperative coalesced load of K,V tiles (float4, contiguous per row)
    const int nf4 = W_ * HD_ / 4;   // 4096 float4
    for (int idx = tid; idx < nf4; idx += 512) {
        int row = idx >> 4;         // HD_/4 = 16 float4 per row
        int d4  = idx & 15;
        ((float4*)Ks)[idx] = *((const float4*)(Kg + base + (size_t)row * C_) + d4);
        ((float4*)Vs)[idx] = *((const float4*)(Vg + base + (size_t)row * C_) + d4);
    }

    const int qi = tid >> 1;        // query row 0..255
    const int hf = tid & 1;         // which 32-dim half

    float q[32];
    {
        const float4* qp = (const float4*)(Q + base + (size_t)qi * C_ + hf * 32);
#pragma unroll
        for (int j = 0; j < 8; j++) *(float4*)&q[j * 4] = qp[j];
    }
    __syncthreads();

    float m = -1e30f, l = 0.f;
    float o[32];
#pragma unroll
    for (int d = 0; d < 32; d++) o[d] = 0.f;
    const float scale = 0.125f;     // 1/sqrt(64)

    for (int kj = 0; kj < W_; kj++) {
        const float* kr = Ks + kj * HD_ + hf * 32;
        float p = 0.f;
#pragma unroll
        for (int j = 0; j < 8; j++) {
            float4 kv = *(const float4*)(kr + j * 4);
            p += q[j*4+0] * kv.x + q[j*4+1] * kv.y + q[j*4+2] * kv.z + q[j*4+3] * kv.w;
        }
        float s = (p + __shfl_xor_sync(0xffffffffu, p, 1)) * scale;

        float mn   = fmaxf(m, s);
        float corr = __expf(m - mn);
        float pe   = __expf(s - mn);
        l = l * corr + pe;

        const float* vr = Vs + kj * HD_ + hf * 32;
#pragma unroll
        for (int j = 0; j < 8; j++) {
            float4 vv = *(const float4*)(vr + j * 4);
            o[j*4+0] = o[j*4+0] * corr + pe * vv.x;
            o[j*4+1] = o[j*4+1] * corr + pe * vv.y;
            o[j*4+2] = o[j*4+2] * corr + pe * vv.z;
            o[j*4+3] = o[j*4+3] * corr + pe * vv.w;
        }
        m = mn;
    }

    float inv = 1.f / l;
    float* dst = Y + base + (size_t)qi * C_ + hf * 32;
#pragma unroll
    for (int j = 0; j < 8; j++) {
        float4 v = make_float4(o[j*4+0]*inv, o[j*4+1]*inv, o[j*4+2]*inv, o[j*4+3]*inv);
        *(float4*)(dst + j * 4) = v;
    }
}

// ---------------------------------------------------------------------------
extern "C" void kernel_launch(void* const* d_in, const int* in_sizes, int n_in,
                              void* d_out, int out_size)
{
    const float* x  = (const float*)d_in[0];
    const float* wq = (const float*)d_in[1];
    const float* wk = (const float*)d_in[2];
    const float* wv = (const float*)d_in[3];
    const float* wo = (const float*)d_in[4];
    float* out = (float*)d_out;

    float *q, *k, *v, *y;
    cudaGetSymbolAddress((void**)&q, g_q);
    cudaGetSymbolAddress((void**)&k, g_k);
    cudaGetSymbolAddress((void**)&v, g_v);
    cudaGetSymbolAddress((void**)&y, g_y);

    dim3 gg(C_ / 128, M_ / 128);
    gemm_nt<1><<<gg, 256>>>(x, wq, q, M_, C_, C_);
    gemm_nt<1><<<gg, 256>>>(x, wk, k, M_, C_, C_);
    gemm_nt<0><<<gg, 256>>>(x, wv, v, M_, C_, C_);

    const int smemBytes = 2 * W_ * HD_ * (int)sizeof(float); // 131072
    cudaFuncSetAttribute(attn_win, cudaFuncAttributeMaxDynamicSharedMemorySize, smemBytes);
    dim3 ga(NW_, H_, B_);
    attn_win<<<ga, 512, smemBytes>>>(q, k, v, y);

    gemm_nt<0><<<gg, 256>>>(y, wo, out, M_, C_, C_);
}

// round 3
// speedup vs baseline: 1.0017x; 1.0004x over previous
#include <cuda_runtime.h>
#include <math.h>

#define B_  2
#define T_  4096
#define C_  1024
#define H_  16
#define HD_ 64
#define W_  256
#define NW_ (T_/W_)
#define M_  (B_*T_)

// Scratch (no cudaMalloc allowed)
__device__ float g_q[(size_t)M_*C_];
__device__ float g_k[(size_t)M_*C_];
__device__ float g_v[(size_t)M_*C_];
__device__ float g_y[(size_t)M_*C_];

// ---------------------------------------------------------------------------
// SGEMM (NT): C[m][n] = sum_k A[m][k] * Wt[n][k]
// A: [M,K] row-major, Wt: [N,K] row-major (both K-contiguous -> coalesced).
// Tile 128x128x32, 256 threads, 8x8 register blocking (4+4 split rows/cols).
// ROPE=1: apply rotary embedding in the epilogue (pairs along n, t = m % T_).
// ---------------------------------------------------------------------------
template<int ROPE>
__global__ __launch_bounds__(256, 2)
void gemm_nt(const float* __restrict__ A, const float* __restrict__ Wt,
             float* __restrict__ Cout, int M, int N, int K)
{
    const int BM = 128, BN = 128, BK = 32;
    __shared__ float As[BK][BM];
    __shared__ float Bs[BK][BN];

    const int tid = threadIdx.x;
    const int m0 = blockIdx.y * BM;
    const int n0 = blockIdx.x * BN;

    // global-load mapping: 32 rows per pass, 8 float4 per row (128B contiguous/row)
    const int lr = tid >> 3;          // row 0..31 within pass
    const int lc = (tid & 7) * 4;     // k offset 0..28

    // compute mapping
    const int tx = tid & 15;          // 16 col-threads
    const int ty = tid >> 4;          // 16 row-threads

    float acc[8][8];
#pragma unroll
    for (int i = 0; i < 8; i++)
#pragma unroll
        for (int j = 0; j < 8; j++) acc[i][j] = 0.f;

    for (int k0 = 0; k0 < K; k0 += BK) {
#pragma unroll
        for (int p = 0; p < 4; p++) {
            int r = lr + p * 32;
            float4 va = *(const float4*)(A + (size_t)(m0 + r) * K + k0 + lc);
            As[lc + 0][r] = va.x; As[lc + 1][r] = va.y;
            As[lc + 2][r] = va.z; As[lc + 3][r] = va.w;
            float4 vb = *(const float4*)(Wt + (size_t)(n0 + r) * K + k0 + lc);
            Bs[lc + 0][r] = vb.x; Bs[lc + 1][r] = vb.y;
            Bs[lc + 2][r] = vb.z; Bs[lc + 3][r] = vb.w;
        }
        __syncthreads();

#pragma unroll
        for (int kk = 0; kk < BK; kk++) {
            float a[8], b[8];
            *(float4*)&a[0] = *(const float4*)&As[kk][ty * 4];
            *(float4*)&a[4] = *(const float4*)&As[kk][ty * 4 + 64];
            *(float4*)&b[0] = *(const float4*)&Bs[kk][tx * 4];
            *(float4*)&b[4] = *(const float4*)&Bs[kk][tx * 4 + 64];
#pragma unroll
            for (int i = 0; i < 8; i++)
#pragma unroll
                for (int j = 0; j < 8; j++)
                    acc[i][j] += a[i] * b[j];
        }
        __syncthreads();
    }

    if (ROPE) {
        // inv_freq per column-pair (4 pairs per thread along n), hoisted, double-exact
        float invf[4];
#pragma unroll
        for (int jp = 0; jp < 4; jp++) {
            int j = jp * 2;
            int nn = n0 + (tx << 2) + (j & 3) + ((j & 4) << 4);
            int ip = (nn & (HD_ - 1)) >> 1;   // 0..31
            invf[jp] = (float)exp(-0.28782313662425572 * (double)ip); // ln(1e4)/32
        }
#pragma unroll
        for (int i = 0; i < 8; i++) {
            int mm = m0 + (ty << 2) + (i & 3) + ((i & 4) << 4);
            float tpos = (float)(mm & (T_ - 1));
#pragma unroll
            for (int jp = 0; jp < 4; jp++) {
                int j = jp * 2;
                int nn = n0 + (tx << 2) + (j & 3) + ((j & 4) << 4);
                float sv, cv;
                sincosf(tpos * invf[jp], &sv, &cv);
                float x1 = acc[i][j], x2 = acc[i][j + 1];
                Cout[(size_t)mm * N + nn]     = x1 * cv - x2 * sv;
                Cout[(size_t)mm * N + nn + 1] = x1 * sv + x2 * cv;
            }
        }
    } else {
#pragma unroll
        for (int i = 0; i < 8; i++) {
            int mm = m0 + (ty << 2) + (i & 3) + ((i & 4) << 4);
#pragma unroll
            for (int j = 0; j < 8; j++) {
                int nn = n0 + (tx << 2) + (j & 3) + ((j & 4) << 4);
                Cout[(size_t)mm * N + nn] = acc[i][j];
            }
        }
    }
}

// ---------------------------------------------------------------------------
// Windowed attention. Grid (nW, H, B). 512 threads: 2 threads / query row,
// each covers 32 of the 64 head dims. K,V staged in 131KB dynamic smem.
// Online (streaming) softmax, output normalized and written to [B,T,C].
// ---------------------------------------------------------------------------
__global__ __launch_bounds__(512, 1)
void attn_win(const float* __restrict__ Q, const float* __restrict__ Kg,
              const float* __restrict__ Vg, float* __restrict__ Y)
{
    extern __shared__ float sm[];
    float* Ks = sm;                 // [256][64]
    float* Vs = sm + W_ * HD_;      // [256][64]

    const int w = blockIdx.x, h = blockIdx.y, b = blockIdx.z;
    const int tid = threadIdx.x;
    const size_t base = ((size_t)(b * T_ + w * W_)) * C_ + h * HD_;

    // cooperative coalesced load of K,V tiles (float4, contiguous per row)
    const int nf4 = W_ * HD_ / 4;   // 4096 float4
    for (int idx = tid; idx < nf4; idx += 512) {
        int row = idx >> 4;         // HD_/4 = 16 float4 per row
        int d4  = idx & 15;
        ((float4*)Ks)[idx] = *((const float4*)(Kg + base + (size_t)row * C_) + d4);
        ((float4*)Vs)[idx] = *((const float4*)(Vg + base + (size_t)row * C_) + d4);
    }

    const int qi = tid >> 1;        // query row 0..255
    const int hf = tid & 1;         // which 32-dim half

    float q[32];
    {
        const float4* qp = (const float4*)(Q + base + (size_t)qi * C_ + hf * 32);
#pragma unroll
        for (int j = 0; j < 8; j++) *(float4*)&q[j * 4] = qp[j];
    }
    __syncthreads();

    float m = -1e30f, l = 0.f;
    float o[32];
#pragma unroll
    for (int d = 0; d < 32; d++) o[d] = 0.f;
    const float scale = 0.125f;     // 1/sqrt(64)

    for (int kj = 0; kj < W_; kj++) {
        const float* kr = Ks + kj * HD_ + hf * 32;
        float p = 0.f;
#pragma unroll
        for (int j = 0; j < 8; j++) {
            float4 kv = *(const float4*)(kr + j * 4);
            p += q[j*4+0] * kv.x + q[j*4+1] * kv.y + q[j*4+2] * kv.z + q[j*4+3] * kv.w;
        }
        float s = (p + __shfl_xor_sync(0xffffffffu, p, 1)) * scale;

        float mn   = fmaxf(m, s);
        float corr = __expf(m - mn);
        float pe   = __expf(s - mn);
        l = l * corr + pe;

        const float* vr = Vs + kj * HD_ + hf * 32;
#pragma unroll
        for (int j = 0; j < 8; j++) {
            float4 vv = *(const float4*)(vr + j * 4);
            o[j*4+0] = o[j*4+0] * corr + pe * vv.x;
            o[j*4+1] = o[j*4+1] * corr + pe * vv.y;
            o[j*4+2] = o[j*4+2] * corr + pe * vv.z;
            o[j*4+3] = o[j*4+3] * corr + pe * vv.w;
        }
        m = mn;
    }

    float inv = 1.f / l;
    float* dst = Y + base + (size_t)qi * C_ + hf * 32;
#pragma unroll
    for (int j = 0; j < 8; j++) {
        float4 v = make_float4(o[j*4+0]*inv, o[j*4+1]*inv, o[j*4+2]*inv, o[j*4+3]*inv);
        *(float4*)(dst + j * 4) = v;
    }
}

// ---------------------------------------------------------------------------
extern "C" void kernel_launch(void* const* d_in, const int* in_sizes, int n_in,
                              void* d_out, int out_size)
{
    const float* x  = (const float*)d_in[0];
    const float* wq = (const float*)d_in[1];
    const float* wk = (const float*)d_in[2];
    const float* wv = (const float*)d_in[3];
    const float* wo = (const float*)d_in[4];
    float* out = (float*)d_out;

    float *q, *k, *v, *y;
    cudaGetSymbolAddress((void**)&q, g_q);
    cudaGetSymbolAddress((void**)&k, g_k);
    cudaGetSymbolAddress((void**)&v, g_v);
    cudaGetSymbolAddress((void**)&y, g_y);

    dim3 gg(C_ / 128, M_ / 128);
    gemm_nt<1><<<gg, 256>>>(x, wq, q, M_, C_, C_);
    gemm_nt<1><<<gg, 256>>>(x, wk, k, M_, C_, C_);
    gemm_nt<0><<<gg, 256>>>(x, wv, v, M_, C_, C_);

    const int smemBytes = 2 * W_ * HD_ * (int)sizeof(float); // 131072
    cudaFuncSetAttribute(attn_win, cudaFuncAttributeMaxDynamicSharedMemorySize, smemBytes);
    dim3 ga(NW_, H_, B_);
    attn_win<<<ga, 512, smemBytes>>>(q, k, v, y);

    gemm_nt<0><<<gg, 256>>>(y, wo, out, M_, C_, C_);
}

// round 5
// speedup vs baseline: 1.8302x; 1.8271x over previous
#include <cuda_runtime.h>
#include <math.h>
#include <stdint.h>

#define B_  2
#define T_  4096
#define C_  1024
#define H_  16
#define HD_ 64
#define W_  256
#define NW_ (T_/W_)
#define M_  (B_*T_)

// Scratch (no cudaMalloc allowed)
__device__ float g_q[(size_t)M_*C_];
__device__ float g_k[(size_t)M_*C_];
__device__ float g_v[(size_t)M_*C_];
__device__ float g_y[(size_t)M_*C_];

// ===========================================================================
// tf32 helpers (baseline ISA — no sm_103a-only features!)
// ===========================================================================
__device__ __forceinline__ uint32_t f2tf32(float f) {
    uint32_t r;
    asm("cvt.rna.tf32.f32 %0, %1;" : "=r"(r) : "f"(f));
    return r;
}

// m16n8k8 tf32 MMA, D += A*B (row.col), fp32 accumulate
__device__ __forceinline__ void mma_tf32(float* d, const uint32_t* a, const uint32_t* b) {
    asm volatile(
        "mma.sync.aligned.m16n8k8.row.col.f32.tf32.tf32.f32 "
        "{%0,%1,%2,%3}, {%4,%5,%6,%7}, {%8,%9}, {%0,%1,%2,%3};"
        : "+f"(d[0]), "+f"(d[1]), "+f"(d[2]), "+f"(d[3])
        : "r"(a[0]), "r"(a[1]), "r"(a[2]), "r"(a[3]),
          "r"(b[0]), "r"(b[1]));
}

// ===========================================================================
// tf32 GEMM (NT): C[m][n] = sum_k A[m][k] * Wt[n][k]
// CTA 128x128, BK=32 double-buffered. 256 threads = 8 warps (2 x 4),
// warp tile 64x32 -> 4x4 = 16 m16n8k8 MMAs, 64 accum regs/lane.
// Smem tiles stored natural-major with row stride 36 floats (pad 4):
// fragment LDS bank = (4g+tig)%32 -> conflict-free.
// ROPE=1: rotary embedding fused into epilogue (acc pairs are RoPE pairs).
// ===========================================================================
#define SA 36                         // smem row stride in floats
#define TILE_F (128 * SA)             // floats per tile buffer (4608)
#define GEMM_SMEM_BYTES (4 * TILE_F * 4)  // A0,A1,B0,B1 = 73728 B

template<int ROPE>
__global__ __launch_bounds__(256)
void gemm_mma(const float* __restrict__ A, const float* __restrict__ Wt,
              float* __restrict__ Cout)
{
    extern __shared__ float sm[];
    float* smA = sm;                  // [2][TILE_F]
    float* smB = sm + 2 * TILE_F;     // [2][TILE_F]

    const int tid  = threadIdx.x;
    const int wid  = tid >> 5, lane = tid & 31;
    const int wm   = wid >> 2, wn = wid & 3;     // 2 x 4 warp grid
    const int g    = lane >> 2, tig = lane & 3;  // mma fragment coords
    const int m0   = blockIdx.y * 128, n0 = blockIdx.x * 128;

    // global load mapping: row = tid>>1 (0..127), half = tid&1 (two 16-float halves)
    const int row  = tid >> 1;
    const int half = tid & 1;
    const float* Ag = A  + (size_t)(m0 + row) * C_ + half * 16;
    const float* Bg = Wt + (size_t)(n0 + row) * C_ + half * 16;
    float* stA = smA + row * SA + half * 16;
    float* stB = smB + row * SA + half * 16;

    float acc[16][4];
#pragma unroll
    for (int i = 0; i < 16; i++)
#pragma unroll
        for (int j = 0; j < 4; j++) acc[i][j] = 0.f;

    float4 ra[4], rb[4];

    // prologue: load chunk 0, convert, store to buf 0
#pragma unroll
    for (int j = 0; j < 4; j++) {
        ra[j] = *(const float4*)(Ag + j * 4);
        rb[j] = *(const float4*)(Bg + j * 4);
    }
#pragma unroll
    for (int j = 0; j < 4; j++) {
        ((uint4*)(stA + j * 4))[0] = make_uint4(f2tf32(ra[j].x), f2tf32(ra[j].y),
                                                f2tf32(ra[j].z), f2tf32(ra[j].w));
        ((uint4*)(stB + j * 4))[0] = make_uint4(f2tf32(rb[j].x), f2tf32(rb[j].y),
                                                f2tf32(rb[j].z), f2tf32(rb[j].w));
    }
    __syncthreads();

    for (int c = 0; c < 32; c++) {           // 32 K-chunks of 32
        const int buf = c & 1;
        // prefetch next chunk into registers while computing this one
        if (c < 31) {
            const int k0 = (c + 1) * 32;
#pragma unroll
            for (int j = 0; j < 4; j++) {
                ra[j] = *(const float4*)(Ag + k0 + j * 4);
                rb[j] = *(const float4*)(Bg + k0 + j * 4);
            }
        }

        const uint32_t* sA = (const uint32_t*)(smA + buf * TILE_F + (wm * 64) * SA);
        const uint32_t* sB = (const uint32_t*)(smB + buf * TILE_F + (wn * 32) * SA);
#pragma unroll
        for (int ks = 0; ks < 4; ks++) {     // 4 k-steps of 8
            const int kb = ks * 8;
            uint32_t afr[4][4], bfr[4][2];
#pragma unroll
            for (int mt = 0; mt < 4; mt++) {
                const uint32_t* p = sA + (mt * 16 + g) * SA + kb + tig;
                afr[mt][0] = p[0];
                afr[mt][1] = p[8 * SA];
                afr[mt][2] = p[4];
                afr[mt][3] = p[8 * SA + 4];
            }
#pragma unroll
            for (int nt = 0; nt < 4; nt++) {
                const uint32_t* p = sB + (nt * 8 + g) * SA + kb + tig;
                bfr[nt][0] = p[0];
                bfr[nt][1] = p[4];
            }
#pragma unroll
            for (int mt = 0; mt < 4; mt++)
#pragma unroll
                for (int nt = 0; nt < 4; nt++)
                    mma_tf32(acc[mt * 4 + nt], afr[mt], bfr[nt]);
        }

        if (c < 31) {
            __syncthreads();                 // everyone done reading buf^1
            float* dA = smA + (buf ^ 1) * TILE_F + row * SA + half * 16;
            float* dB = smB + (buf ^ 1) * TILE_F + row * SA + half * 16;
#pragma unroll
            for (int j = 0; j < 4; j++) {
                ((uint4*)(dA + j * 4))[0] = make_uint4(f2tf32(ra[j].x), f2tf32(ra[j].y),
                                                       f2tf32(ra[j].z), f2tf32(ra[j].w));
                ((uint4*)(dB + j * 4))[0] = make_uint4(f2tf32(rb[j].x), f2tf32(rb[j].y),
                                                       f2tf32(rb[j].z), f2tf32(rb[j].w));
            }
            __syncthreads();
        }
    }

    // -------- epilogue --------
    const int mbase = m0 + wm * 64;
    const int nbase = n0 + wn * 32;
#pragma unroll
    for (int nt = 0; nt < 4; nt++) {
        const int nn = nbase + nt * 8 + 2 * tig;
        float invf = 1.f, sv0, cv0, sv1, cv1;
        if (ROPE) {
            const int ip = (nn & (HD_ - 1)) >> 1;   // 0..31
            invf = (float)exp(-0.28782313662425572 * (double)ip); // ln(1e4)/32
        }
#pragma unroll
        for (int mt = 0; mt < 4; mt++) {
            const float* cc = acc[mt * 4 + nt];
            const int r0 = mbase + mt * 16 + g;
            const int r1 = r0 + 8;
            float2 v01 = make_float2(cc[0], cc[1]);
            float2 v23 = make_float2(cc[2], cc[3]);
            if (ROPE) {
                sincosf((float)(r0 & (T_ - 1)) * invf, &sv0, &cv0);
                sincosf((float)(r1 & (T_ - 1)) * invf, &sv1, &cv1);
                v01 = make_float2(cc[0] * cv0 - cc[1] * sv0,
                                  cc[0] * sv0 + cc[1] * cv0);
                v23 = make_float2(cc[2] * cv1 - cc[3] * sv1,
                                  cc[2] * sv1 + cc[3] * cv1);
            }
            *(float2*)(Cout + (size_t)r0 * C_ + nn) = v01;
            *(float2*)(Cout + (size_t)r1 * C_ + nn) = v23;
        }
    }
}

// ===========================================================================
// Windowed attention. Grid (nW, H, B), 512 threads.
// Thread (qg, sub): qg = tid>>2 handles queries 2qg, 2qg+1; sub = tid&3 owns
// dims [sub*16, sub*16+16). K/V fragments broadcast across query groups,
// score reduced over the 4-thread dim group via shfl_xor. 4x less LDS than v1.
// ===========================================================================
__global__ __launch_bounds__(512, 1)
void attn_win(const float* __restrict__ Q, const float* __restrict__ Kg,
              const float* __restrict__ Vg, float* __restrict__ Y)
{
    extern __shared__ float smf[];
    float* Ks = smf;                 // [256][64]
    float* Vs = smf + W_ * HD_;      // [256][64]

    const int w = blockIdx.x, h = blockIdx.y, b = blockIdx.z;
    const int tid = threadIdx.x;
    const size_t base = ((size_t)(b * T_ + w * W_)) * C_ + h * HD_;

    const int nf4 = W_ * HD_ / 4;    // 4096
    for (int idx = tid; idx < nf4; idx += 512) {
        int row = idx >> 4, d4 = idx & 15;
        ((float4*)Ks)[idx] = *((const float4*)(Kg + base + (size_t)row * C_) + d4);
        ((float4*)Vs)[idx] = *((const float4*)(Vg + base + (size_t)row * C_) + d4);
    }

    const int qg  = tid >> 2;        // 0..127
    const int sub = tid & 3;         // dim slice
    const int q0  = qg * 2;

    float q[2][16];
#pragma unroll
    for (int g = 0; g < 2; g++) {
        const float4* qp = (const float4*)(Q + base + (size_t)(q0 + g) * C_ + sub * 16);
#pragma unroll
        for (int j = 0; j < 4; j++) *(float4*)&q[g][j * 4] = qp[j];
    }
    __syncthreads();

    float m0v = -1e30f, m1v = -1e30f, l0 = 0.f, l1 = 0.f;
    float o[2][16];
#pragma unroll
    for (int g = 0; g < 2; g++)
#pragma unroll
        for (int d = 0; d < 16; d++) o[g][d] = 0.f;
    const float scale = 0.125f;

    for (int kj = 0; kj < W_; kj++) {
        const float4* kr = (const float4*)(Ks + kj * HD_ + sub * 16);
        float p0 = 0.f, p1 = 0.f;
#pragma unroll
        for (int j = 0; j < 4; j++) {
            float4 kv = kr[j];
            p0 += q[0][j*4+0]*kv.x + q[0][j*4+1]*kv.y + q[0][j*4+2]*kv.z + q[0][j*4+3]*kv.w;
            p1 += q[1][j*4+0]*kv.x + q[1][j*4+1]*kv.y + q[1][j*4+2]*kv.z + q[1][j*4+3]*kv.w;
        }
        p0 += __shfl_xor_sync(0xffffffffu, p0, 1);
        p0 += __shfl_xor_sync(0xffffffffu, p0, 2);
        p1 += __shfl_xor_sync(0xffffffffu, p1, 1);
        p1 += __shfl_xor_sync(0xffffffffu, p1, 2);

        float s0 = p0 * scale, s1 = p1 * scale;
        float mn0 = fmaxf(m0v, s0), mn1 = fmaxf(m1v, s1);
        float c0 = __expf(m0v - mn0), c1 = __expf(m1v - mn1);
        float e0 = __expf(s0 - mn0),  e1 = __expf(s1 - mn1);
        l0 = l0 * c0 + e0;  l1 = l1 * c1 + e1;
        m0v = mn0;  m1v = mn1;

        const float4* vr = (const float4*)(Vs + kj * HD_ + sub * 16);
#pragma unroll
        for (int j = 0; j < 4; j++) {
            float4 vv = vr[j];
            o[0][j*4+0] = o[0][j*4+0]*c0 + e0*vv.x;
            o[0][j*4+1] = o[0][j*4+1]*c0 + e0*vv.y;
            o[0][j*4+2] = o[0][j*4+2]*c0 + e0*vv.z;
            o[0][j*4+3] = o[0][j*4+3]*c0 + e0*vv.w;
            o[1][j*4+0] = o[1][j*4+0]*c1 + e1*vv.x;
            o[1][j*4+1] = o[1][j*4+1]*c1 + e1*vv.y;
            o[1][j*4+2] = o[1][j*4+2]*c1 + e1*vv.z;
            o[1][j*4+3] = o[1][j*4+3]*c1 + e1*vv.w;
        }
    }

    float i0 = 1.f / l0, i1 = 1.f / l1;
#pragma unroll
    for (int g = 0; g < 2; g++) {
        float inv = g ? i1 : i0;
        float* dst = Y + base + (size_t)(q0 + g) * C_ + sub * 16;
#pragma unroll
        for (int j = 0; j < 4; j++) {
            float4 v = make_float4(o[g][j*4+0]*inv, o[g][j*4+1]*inv,
                                   o[g][j*4+2]*inv, o[g][j*4+3]*inv);
            *(float4*)(dst + j * 4) = v;
        }
    }
}

// ===========================================================================
extern "C" void kernel_launch(void* const* d_in, const int* in_sizes, int n_in,
                              void* d_out, int out_size)
{
    const float* x  = (const float*)d_in[0];
    const float* wq = (const float*)d_in[1];
    const float* wk = (const float*)d_in[2];
    const float* wv = (const float*)d_in[3];
    const float* wo = (const float*)d_in[4];
    float* out = (float*)d_out;

    float *q, *k, *v, *y;
    cudaGetSymbolAddress((void**)&q, g_q);
    cudaGetSymbolAddress((void**)&k, g_k);
    cudaGetSymbolAddress((void**)&v, g_v);
    cudaGetSymbolAddress((void**)&y, g_y);

    cudaFuncSetAttribute(gemm_mma<1>, cudaFuncAttributeMaxDynamicSharedMemorySize, GEMM_SMEM_BYTES);
    cudaFuncSetAttribute(gemm_mma<0>, cudaFuncAttributeMaxDynamicSharedMemorySize, GEMM_SMEM_BYTES);
    const int smemAttn = 2 * W_ * HD_ * (int)sizeof(float); // 131072
    cudaFuncSetAttribute(attn_win, cudaFuncAttributeMaxDynamicSharedMemorySize, smemAttn);

    dim3 gg(C_ / 128, M_ / 128);   // (8, 64)
    gemm_mma<1><<<gg, 256, GEMM_SMEM_BYTES>>>(x, wq, q);
    gemm_mma<1><<<gg, 256, GEMM_SMEM_BYTES>>>(x, wk, k);
    gemm_mma<0><<<gg, 256, GEMM_SMEM_BYTES>>>(x, wv, v);

    dim3 ga(NW_, H_, B_);
    attn_win<<<ga, 512, smemAttn>>>(q, k, v, y);

    gemm_mma<0><<<gg, 256, GEMM_SMEM_BYTES>>>(y, wo, out);
}

// round 7
// speedup vs baseline: 2.5919x; 1.4162x over previous
#include <cuda_runtime.h>
#include <math.h>
#include <stdint.h>

#define B_  2
#define T_  4096
#define C_  1024
#define H_  16
#define HD_ 64
#define W_  256
#define NW_ (T_/W_)
#define M_  (B_*T_)

// Scratch (no cudaMalloc allowed)
__device__ float g_q[(size_t)M_*C_];
__device__ float g_k[(size_t)M_*C_];
__device__ float g_v[(size_t)M_*C_];
__device__ float g_y[(size_t)M_*C_];

// ===========================================================================
// tf32 helpers (baseline ISA)
// ===========================================================================
__device__ __forceinline__ uint32_t f2tf32(float f) {
    uint32_t r;
    asm("cvt.rna.tf32.f32 %0, %1;" : "=r"(r) : "f"(f));
    return r;
}

// m16n8k8 tf32 MMA, D += A*B (row.col), fp32 accumulate
__device__ __forceinline__ void mma_tf32(float* d, const uint32_t* a, const uint32_t* b) {
    asm volatile(
        "mma.sync.aligned.m16n8k8.row.col.f32.tf32.tf32.f32 "
        "{%0,%1,%2,%3}, {%4,%5,%6,%7}, {%8,%9}, {%0,%1,%2,%3};"
        : "+f"(d[0]), "+f"(d[1]), "+f"(d[2]), "+f"(d[3])
        : "r"(a[0]), "r"(a[1]), "r"(a[2]), "r"(a[3]),
          "r"(b[0]), "r"(b[1]));
}

// ===========================================================================
// tf32 GEMM (NT): C[m][n] = sum_k A[m][k] * Wt[n][k]   (unchanged: passed R5)
// ===========================================================================
#define SA 36
#define TILE_F (128 * SA)
#define GEMM_SMEM_BYTES (4 * TILE_F * 4)

template<int ROPE>
__global__ __launch_bounds__(256)
void gemm_mma(const float* __restrict__ A, const float* __restrict__ Wt,
              float* __restrict__ Cout)
{
    extern __shared__ float sm[];
    float* smA = sm;
    float* smB = sm + 2 * TILE_F;

    const int tid  = threadIdx.x;
    const int wid  = tid >> 5, lane = tid & 31;
    const int wm   = wid >> 2, wn = wid & 3;
    const int g    = lane >> 2, tig = lane & 3;
    const int m0   = blockIdx.y * 128, n0 = blockIdx.x * 128;

    const int row  = tid >> 1;
    const int half = tid & 1;
    const float* Ag = A  + (size_t)(m0 + row) * C_ + half * 16;
    const float* Bg = Wt + (size_t)(n0 + row) * C_ + half * 16;
    float* stA = smA + row * SA + half * 16;
    float* stB = smB + row * SA + half * 16;

    float acc[16][4];
#pragma unroll
    for (int i = 0; i < 16; i++)
#pragma unroll
        for (int j = 0; j < 4; j++) acc[i][j] = 0.f;

    float4 ra[4], rb[4];

#pragma unroll
    for (int j = 0; j < 4; j++) {
        ra[j] = *(const float4*)(Ag + j * 4);
        rb[j] = *(const float4*)(Bg + j * 4);
    }
#pragma unroll
    for (int j = 0; j < 4; j++) {
        ((uint4*)(stA + j * 4))[0] = make_uint4(f2tf32(ra[j].x), f2tf32(ra[j].y),
                                                f2tf32(ra[j].z), f2tf32(ra[j].w));
        ((uint4*)(stB + j * 4))[0] = make_uint4(f2tf32(rb[j].x), f2tf32(rb[j].y),
                                                f2tf32(rb[j].z), f2tf32(rb[j].w));
    }
    __syncthreads();

    for (int c = 0; c < 32; c++) {
        const int buf = c & 1;
        if (c < 31) {
            const int k0 = (c + 1) * 32;
#pragma unroll
            for (int j = 0; j < 4; j++) {
                ra[j] = *(const float4*)(Ag + k0 + j * 4);
                rb[j] = *(const float4*)(Bg + k0 + j * 4);
            }
        }

        const uint32_t* sA = (const uint32_t*)(smA + buf * TILE_F + (wm * 64) * SA);
        const uint32_t* sB = (const uint32_t*)(smB + buf * TILE_F + (wn * 32) * SA);
#pragma unroll
        for (int ks = 0; ks < 4; ks++) {
            const int kb = ks * 8;
            uint32_t afr[4][4], bfr[4][2];
#pragma unroll
            for (int mt = 0; mt < 4; mt++) {
                const uint32_t* p = sA + (mt * 16 + g) * SA + kb + tig;
                afr[mt][0] = p[0];
                afr[mt][1] = p[8 * SA];
                afr[mt][2] = p[4];
                afr[mt][3] = p[8 * SA + 4];
            }
#pragma unroll
            for (int nt = 0; nt < 4; nt++) {
                const uint32_t* p = sB + (nt * 8 + g) * SA + kb + tig;
                bfr[nt][0] = p[0];
                bfr[nt][1] = p[4];
            }
#pragma unroll
            for (int mt = 0; mt < 4; mt++)
#pragma unroll
                for (int nt = 0; nt < 4; nt++)
                    mma_tf32(acc[mt * 4 + nt], afr[mt], bfr[nt]);
        }

        if (c < 31) {
            __syncthreads();
            float* dA = smA + (buf ^ 1) * TILE_F + row * SA + half * 16;
            float* dB = smB + (buf ^ 1) * TILE_F + row * SA + half * 16;
#pragma unroll
            for (int j = 0; j < 4; j++) {
                ((uint4*)(dA + j * 4))[0] = make_uint4(f2tf32(ra[j].x), f2tf32(ra[j].y),
                                                       f2tf32(ra[j].z), f2tf32(ra[j].w));
                ((uint4*)(dB + j * 4))[0] = make_uint4(f2tf32(rb[j].x), f2tf32(rb[j].y),
                                                       f2tf32(rb[j].z), f2tf32(rb[j].w));
            }
            __syncthreads();
        }
    }

    const int mbase = m0 + wm * 64;
    const int nbase = n0 + wn * 32;
#pragma unroll
    for (int nt = 0; nt < 4; nt++) {
        const int nn = nbase + nt * 8 + 2 * tig;
        float invf = 1.f, sv0, cv0, sv1, cv1;
        if (ROPE) {
            const int ip = (nn & (HD_ - 1)) >> 1;
            invf = (float)exp(-0.28782313662425572 * (double)ip);
        }
#pragma unroll
        for (int mt = 0; mt < 4; mt++) {
            const float* cc = acc[mt * 4 + nt];
            const int r0 = mbase + mt * 16 + g;
            const int r1 = r0 + 8;
            float2 v01 = make_float2(cc[0], cc[1]);
            float2 v23 = make_float2(cc[2], cc[3]);
            if (ROPE) {
                sincosf((float)(r0 & (T_ - 1)) * invf, &sv0, &cv0);
                sincosf((float)(r1 & (T_ - 1)) * invf, &sv1, &cv1);
                v01 = make_float2(cc[0] * cv0 - cc[1] * sv0,
                                  cc[0] * sv0 + cc[1] * cv0);
                v23 = make_float2(cc[2] * cv1 - cc[3] * sv1,
                                  cc[2] * sv1 + cc[3] * cv1);
            }
            *(float2*)(Cout + (size_t)r0 * C_ + nn) = v01;
            *(float2*)(Cout + (size_t)r1 * C_ + nn) = v23;
        }
    }
}

// ===========================================================================
// MMA flash-attention, split-tf32 compensated.
// Grid (2*nW, H, B): qseg = bx&1 -> queries [qseg*128, +128). 256 thr = 8 warps,
// warp owns 16 queries. K/V streamed in 32-key chunks, double-buffered, split
// hi/lo tf32. S = Qhi*Khi + Qhi*Klo + Qlo*Khi (~fp32-accurate scores).
// Online softmax; P rounded to tf32, l summed from the ROUNDED P (consistent
// convex combination). O += P*Vhi + P*Vlo.
// ===========================================================================
#define KP 68
#define VP 72
#define PP 36
#define OFF_KHI 0
#define OFF_KLO (OFF_KHI + 2*32*KP)
#define OFF_VHI (OFF_KLO + 2*32*KP)
#define OFF_VLO (OFF_VHI + 2*32*VP)
#define OFF_P   (OFF_VLO + 2*32*VP)
#define ATTN_SMEM_BYTES ((OFF_P + 8*16*PP) * 4)   // 90112

__global__ __launch_bounds__(256)
void attn_mma(const float* __restrict__ Q, const float* __restrict__ Kg,
              const float* __restrict__ Vg, float* __restrict__ Y)
{
    extern __shared__ float smf[];

    const int w = blockIdx.x >> 1, qseg = blockIdx.x & 1;
    const int h = blockIdx.y, b = blockIdx.z;
    const int tid  = threadIdx.x;
    const int wid  = tid >> 5, lane = tid & 31;
    const int g    = lane >> 2, tig = lane & 3;
    const size_t base = ((size_t)(b * T_ + w * W_)) * C_ + h * HD_;

    // ---- staging mapping: 256 threads cover 32 rows x 64 floats ----
    const int srow = tid >> 3;           // 0..31
    const int scol = (tid & 7) * 8;      // 0,8,..,56

    // ---- load Q fragments (16 rows per warp), pre-scaled, hi/lo split ----
    uint32_t qhi[8][4], qlo[8][4];
    {
        const int qb = qseg * 128 + wid * 16;
        const float* Qp = Q + base + (size_t)qb * C_;
#pragma unroll
        for (int ks = 0; ks < 8; ks++) {
            const int cidx = ks * 8 + tig;
            float v0 = 0.125f * Qp[(size_t)g * C_ + cidx];
            float v1 = 0.125f * Qp[(size_t)(g + 8) * C_ + cidx];
            float v2 = 0.125f * Qp[(size_t)g * C_ + cidx + 4];
            float v3 = 0.125f * Qp[(size_t)(g + 8) * C_ + cidx + 4];
            qhi[ks][0] = f2tf32(v0); qlo[ks][0] = f2tf32(v0 - __uint_as_float(qhi[ks][0]));
            qhi[ks][1] = f2tf32(v1); qlo[ks][1] = f2tf32(v1 - __uint_as_float(qhi[ks][1]));
            qhi[ks][2] = f2tf32(v2); qlo[ks][2] = f2tf32(v2 - __uint_as_float(qhi[ks][2]));
            qhi[ks][3] = f2tf32(v3); qlo[ks][3] = f2tf32(v3 - __uint_as_float(qhi[ks][3]));
        }
    }

    // ---- stage chunk 0 into buf 0 ----
    {
        const float* kr = Kg + base + (size_t)srow * C_ + scol;
        const float* vr = Vg + base + (size_t)srow * C_ + scol;
#pragma unroll
        for (int hh = 0; hh < 2; hh++) {
            float4 kv = *(const float4*)(kr + hh * 4);
            uint4 h4, l4;
            h4.x = f2tf32(kv.x); l4.x = f2tf32(kv.x - __uint_as_float(h4.x));
            h4.y = f2tf32(kv.y); l4.y = f2tf32(kv.y - __uint_as_float(h4.y));
            h4.z = f2tf32(kv.z); l4.z = f2tf32(kv.z - __uint_as_float(h4.z));
            h4.w = f2tf32(kv.w); l4.w = f2tf32(kv.w - __uint_as_float(h4.w));
            *(uint4*)(smf + OFF_KHI + srow * KP + scol + hh * 4) = h4;
            *(uint4*)(smf + OFF_KLO + srow * KP + scol + hh * 4) = l4;
            float4 vv = *(const float4*)(vr + hh * 4);
            h4.x = f2tf32(vv.x); l4.x = f2tf32(vv.x - __uint_as_float(h4.x));
            h4.y = f2tf32(vv.y); l4.y = f2tf32(vv.y - __uint_as_float(h4.y));
            h4.z = f2tf32(vv.z); l4.z = f2tf32(vv.z - __uint_as_float(h4.z));
            h4.w = f2tf32(vv.w); l4.w = f2tf32(vv.w - __uint_as_float(h4.w));
            *(uint4*)(smf + OFF_VHI + srow * VP + scol + hh * 4) = h4;
            *(uint4*)(smf + OFF_VLO + srow * VP + scol + hh * 4) = l4;
        }
    }
    __syncthreads();

    float oacc[8][4];
#pragma unroll
    for (int nt = 0; nt < 8; nt++)
#pragma unroll
        for (int j = 0; j < 4; j++) oacc[nt][j] = 0.f;
    float mrow[2] = {-1e30f, -1e30f};
    float lrow[2] = {0.f, 0.f};

    float* Pw = smf + OFF_P + wid * 16 * PP;

    for (int c = 0; c < 8; c++) {
        const int buf = c & 1;

        // ---- prefetch+stage next chunk into buf^1 ----
        if (c < 7) {
            const int kc1 = (c + 1) * 32;
            const float* kr = Kg + base + (size_t)(kc1 + srow) * C_ + scol;
            const float* vr = Vg + base + (size_t)(kc1 + srow) * C_ + scol;
            const int bofK = (buf ^ 1) * 32 * KP + srow * KP + scol;
            const int bofV = (buf ^ 1) * 32 * VP + srow * VP + scol;
#pragma unroll
            for (int hh = 0; hh < 2; hh++) {
                float4 kv = *(const float4*)(kr + hh * 4);
                uint4 h4, l4;
                h4.x = f2tf32(kv.x); l4.x = f2tf32(kv.x - __uint_as_float(h4.x));
                h4.y = f2tf32(kv.y); l4.y = f2tf32(kv.y - __uint_as_float(h4.y));
                h4.z = f2tf32(kv.z); l4.z = f2tf32(kv.z - __uint_as_float(h4.z));
                h4.w = f2tf32(kv.w); l4.w = f2tf32(kv.w - __uint_as_float(h4.w));
                *(uint4*)(smf + OFF_KHI + bofK + hh * 4) = h4;
                *(uint4*)(smf + OFF_KLO + bofK + hh * 4) = l4;
                float4 vv = *(const float4*)(vr + hh * 4);
                h4.x = f2tf32(vv.x); l4.x = f2tf32(vv.x - __uint_as_float(h4.x));
                h4.y = f2tf32(vv.y); l4.y = f2tf32(vv.y - __uint_as_float(h4.y));
                h4.z = f2tf32(vv.z); l4.z = f2tf32(vv.z - __uint_as_float(h4.z));
                h4.w = f2tf32(vv.w); l4.w = f2tf32(vv.w - __uint_as_float(h4.w));
                *(uint4*)(smf + OFF_VHI + bofV + hh * 4) = h4;
                *(uint4*)(smf + OFF_VLO + bofV + hh * 4) = l4;
            }
        }

        // ---- S = Q @ K^T (3-term split tf32) ----
        const uint32_t* Khi = (const uint32_t*)(smf + OFF_KHI + buf * 32 * KP);
        const uint32_t* Klo = (const uint32_t*)(smf + OFF_KLO + buf * 32 * KP);
        float sacc[4][4];
#pragma unroll
        for (int nt = 0; nt < 4; nt++)
#pragma unroll
            for (int j = 0; j < 4; j++) sacc[nt][j] = 0.f;

#pragma unroll
        for (int ks = 0; ks < 8; ks++) {
#pragma unroll
            for (int nt = 0; nt < 4; nt++) {
                const int koff = (nt * 8 + g) * KP + ks * 8 + tig;
                uint32_t bh[2], bl[2];
                bh[0] = Khi[koff];  bh[1] = Khi[koff + 4];
                bl[0] = Klo[koff];  bl[1] = Klo[koff + 4];
                mma_tf32(sacc[nt], qhi[ks], bh);
                mma_tf32(sacc[nt], qhi[ks], bl);
                mma_tf32(sacc[nt], qlo[ks], bh);
            }
        }

        // ---- online softmax; stage tf32-rounded P; l from rounded P ----
#pragma unroll
        for (int rr = 0; rr < 2; rr++) {
            float vmax = sacc[0][rr * 2];
#pragma unroll
            for (int nt = 0; nt < 4; nt++) {
                vmax = fmaxf(vmax, sacc[nt][rr * 2]);
                vmax = fmaxf(vmax, sacc[nt][rr * 2 + 1]);
            }
            vmax = fmaxf(vmax, __shfl_xor_sync(0xffffffffu, vmax, 1));
            vmax = fmaxf(vmax, __shfl_xor_sync(0xffffffffu, vmax, 2));
            const float mnew = fmaxf(mrow[rr], vmax);
            const float corr = __expf(mrow[rr] - mnew);
            float psum = 0.f;
            const int prow = (rr * 8 + g) * PP;
#pragma unroll
            for (int nt = 0; nt < 4; nt++) {
                uint32_t p0 = f2tf32(__expf(sacc[nt][rr * 2]     - mnew));
                uint32_t p1 = f2tf32(__expf(sacc[nt][rr * 2 + 1] - mnew));
                psum += __uint_as_float(p0) + __uint_as_float(p1);
                *(uint2*)(Pw + prow + nt * 8 + 2 * tig) = make_uint2(p0, p1);
            }
            psum += __shfl_xor_sync(0xffffffffu, psum, 1);
            psum += __shfl_xor_sync(0xffffffffu, psum, 2);
            lrow[rr] = lrow[rr] * corr + psum;
            mrow[rr] = mnew;
#pragma unroll
            for (int nt = 0; nt < 8; nt++) {
                oacc[nt][rr * 2]     *= corr;
                oacc[nt][rr * 2 + 1] *= corr;
            }
        }
        __syncwarp();

        // ---- O += P @ (Vhi + Vlo) ----
        const uint32_t* Vhi = (const uint32_t*)(smf + OFF_VHI + buf * 32 * VP);
        const uint32_t* Vlo = (const uint32_t*)(smf + OFF_VLO + buf * 32 * VP);
#pragma unroll
        for (int kt = 0; kt < 4; kt++) {
            uint32_t pa[4];
            const uint32_t* pp = (const uint32_t*)(Pw + g * PP + kt * 8 + tig);
            pa[0] = pp[0];
            pa[1] = pp[8 * PP];
            pa[2] = pp[4];
            pa[3] = pp[8 * PP + 4];
#pragma unroll
            for (int nt = 0; nt < 8; nt++) {
                const int voff = (kt * 8 + tig) * VP + nt * 8 + g;
                uint32_t bv[2];
                bv[0] = Vhi[voff];  bv[1] = Vhi[voff + 4 * VP];
                mma_tf32(oacc[nt], pa, bv);
                bv[0] = Vlo[voff];  bv[1] = Vlo[voff + 4 * VP];
                mma_tf32(oacc[nt], pa, bv);
            }
        }
        __syncthreads();   // all reads of buf done; staged buf^1 visible
    }

    // ---- epilogue: normalize & store ----
    const float inv0 = 1.f / lrow[0], inv1 = 1.f / lrow[1];
    const int qb = qseg * 128 + wid * 16;
    float* Yp = Y + base + (size_t)qb * C_;
#pragma unroll
    for (int nt = 0; nt < 8; nt++) {
        const int d = nt * 8 + 2 * tig;
        *(float2*)(Yp + (size_t)g * C_ + d) =
            make_float2(oacc[nt][0] * inv0, oacc[nt][1] * inv0);
        *(float2*)(Yp + (size_t)(g + 8) * C_ + d) =
            make_float2(oacc[nt][2] * inv1, oacc[nt][3] * inv1);
    }
}

// ===========================================================================
extern "C" void kernel_launch(void* const* d_in, const int* in_sizes, int n_in,
                              void* d_out, int out_size)
{
    const float* x  = (const float*)d_in[0];
    const float* wq = (const float*)d_in[1];
    const float* wk = (const float*)d_in[2];
    const float* wv = (const float*)d_in[3];
    const float* wo = (const float*)d_in[4];
    float* out = (float*)d_out;

    float *q, *k, *v, *y;
    cudaGetSymbolAddress((void**)&q, g_q);
    cudaGetSymbolAddress((void**)&k, g_k);
    cudaGetSymbolAddress((void**)&v, g_v);
    cudaGetSymbolAddress((void**)&y, g_y);

    cudaFuncSetAttribute(gemm_mma<1>, cudaFuncAttributeMaxDynamicSharedMemorySize, GEMM_SMEM_BYTES);
    cudaFuncSetAttribute(gemm_mma<0>, cudaFuncAttributeMaxDynamicSharedMemorySize, GEMM_SMEM_BYTES);
    cudaFuncSetAttribute(attn_mma, cudaFuncAttributeMaxDynamicSharedMemorySize, ATTN_SMEM_BYTES);

    dim3 gg(C_ / 128, M_ / 128);
    gemm_mma<1><<<gg, 256, GEMM_SMEM_BYTES>>>(x, wq, q);
    gemm_mma<1><<<gg, 256, GEMM_SMEM_BYTES>>>(x, wk, k);
    gemm_mma<0><<<gg, 256, GEMM_SMEM_BYTES>>>(x, wv, v);

    dim3 ga(NW_ * 2, H_, B_);
    attn_mma<<<ga, 256, ATTN_SMEM_BYTES>>>(q, k, v, y);

    gemm_mma<0><<<gg, 256, GEMM_SMEM_BYTES>>>(y, wo, out);
}